// round 7
// baseline (speedup 1.0000x reference)
#include <cuda_runtime.h>

// FuzzyARTMAP single fused kernel: match scores + row sums + argmax.
// N=1024, D=256, C=512, fp32. match[n,c] = sum_d min(x,w) / sum_d x; gate 0.75;
// first-occurrence argmax.
//
// R6: packed f32x2 accumulation (Blackwell add.rn.f32x2) — 2 FMNMX + 1 FADD2 per
// k-pair instead of 2+2 scalar, cutting math issue slots 25%. LDG reg-prefetch
// double buffering hides global loads behind compute. 512 threads, 2x4 micro-tile,
// 64x64 block tile, 128 blocks.

#define N_ROWS 1024
#define D_DIM  256
#define C_CATS 512
#define VIG    0.75f

#define BM 64
#define BN 64
#define BK 64
#define NCB (C_CATS / BN)     // column-blocks per row = 8
#define LSTRIDE 68            // 16B-aligned rows

__device__ unsigned long long g_key[N_ROWS];   // zero at load; self-reset each launch
__device__ unsigned int       g_cnt[N_ROWS];   // zero at load; self-reset each launch

// min two scalar pairs, accumulate into a packed f32x2 accumulator.
// ptxas allocates _m0/_m1 as an aligned pair and elides the mov.b64.
#define PMA(A0, A1, B0, B1, ACC) do {                                   \
    float _m0 = fminf((A0), (B0));                                      \
    float _m1 = fminf((A1), (B1));                                      \
    unsigned long long _p;                                              \
    asm("mov.b64 %0, {%1, %2};" : "=l"(_p) : "f"(_m0), "f"(_m1));      \
    asm("add.rn.f32x2 %0, %0, %1;" : "+l"(ACC) : "l"(_p));             \
} while (0)

// ---------------------------------------------------------------------------
__global__ __launch_bounds__(512) void fused_kernel(const float* __restrict__ x,
                                                    const float* __restrict__ w,
                                                    float* __restrict__ out,
                                                    float* __restrict__ idx_out) {
    __shared__ float As[BM][LSTRIDE];             // x tile [m][k]
    __shared__ float Bs[BN][LSTRIDE];             // w tile [c][k]
    __shared__ float xq[BM][8];                   // per-row 1/8 sums of x
    __shared__ unsigned long long skey[BM];       // per-row best (val, col) key

    const int t  = threadIdx.x;
    const int tx = t & 15;        // 16 thread-columns
    const int ty = t >> 4;        // 32 thread-rows (2 rows each)
    const int rowBase = blockIdx.y * BM;
    const int colBase = blockIdx.x * BN;

    // acc2[i][j] holds (sum over even k, sum over odd k) packed as f32x2
    unsigned long long acc2[2][4];
    #pragma unroll
    for (int i = 0; i < 2; i++)
        #pragma unroll
        for (int j = 0; j < 4; j++) acc2[i][j] = 0ull;

    float xpart = 0.f;             // x row-sum duty: 8 threads per row, 8 elems each
    const int xr = t >> 3;
    const int xc = (t & 7) * 8;

    if (t < BM) skey[t] = 0ull;

    // Tile-load mapping: 2 float4 per array per thread.
    const int l0r = t >> 4,          l0c = t & 15;          // first float4
    const int l1r = (t + 512) >> 4,  l1c = t & 15;          // second float4

    // Prefetch iter 0 into registers.
    float4 pa0 = *(const float4*)(x + (size_t)(rowBase + l0r) * D_DIM + 4 * l0c);
    float4 pa1 = *(const float4*)(x + (size_t)(rowBase + l1r) * D_DIM + 4 * l1c);
    float4 pb0 = *(const float4*)(w + (size_t)(colBase + l0r) * D_DIM + 4 * l0c);
    float4 pb1 = *(const float4*)(w + (size_t)(colBase + l1r) * D_DIM + 4 * l1c);

    #pragma unroll
    for (int it = 0; it < D_DIM / BK; it++) {
        *(float4*)&As[l0r][4 * l0c] = pa0;
        *(float4*)&As[l1r][4 * l1c] = pa1;
        *(float4*)&Bs[l0r][4 * l0c] = pb0;
        *(float4*)&Bs[l1r][4 * l1c] = pb1;
        __syncthreads();

        // Prefetch next iteration's tiles (hidden behind the math below).
        if (it + 1 < D_DIM / BK) {
            int k0 = (it + 1) * BK;
            pa0 = *(const float4*)(x + (size_t)(rowBase + l0r) * D_DIM + k0 + 4 * l0c);
            pa1 = *(const float4*)(x + (size_t)(rowBase + l1r) * D_DIM + k0 + 4 * l1c);
            pb0 = *(const float4*)(w + (size_t)(colBase + l0r) * D_DIM + k0 + 4 * l0c);
            pb1 = *(const float4*)(w + (size_t)(colBase + l1r) * D_DIM + k0 + 4 * l1c);
        }

        // Fused row-sum: each thread sums an 8-wide slice of one As row.
        {
            float4 v0 = *(const float4*)&As[xr][xc];
            float4 v1 = *(const float4*)&As[xr][xc + 4];
            xpart += (v0.x + v0.y) + (v0.z + v0.w) + (v1.x + v1.y) + (v1.z + v1.w);
        }

        #pragma unroll 4
        for (int k = 0; k < BK; k += 4) {
            float4 a0 = *(const float4*)&As[2 * ty + 0][k];
            float4 a1 = *(const float4*)&As[2 * ty + 1][k];
            float4 b0 = *(const float4*)&Bs[tx +  0][k];
            float4 b1 = *(const float4*)&Bs[tx + 16][k];
            float4 b2 = *(const float4*)&Bs[tx + 32][k];
            float4 b3 = *(const float4*)&Bs[tx + 48][k];

            PMA(a0.x, a0.y, b0.x, b0.y, acc2[0][0]);
            PMA(a0.z, a0.w, b0.z, b0.w, acc2[0][0]);
            PMA(a0.x, a0.y, b1.x, b1.y, acc2[0][1]);
            PMA(a0.z, a0.w, b1.z, b1.w, acc2[0][1]);
            PMA(a0.x, a0.y, b2.x, b2.y, acc2[0][2]);
            PMA(a0.z, a0.w, b2.z, b2.w, acc2[0][2]);
            PMA(a0.x, a0.y, b3.x, b3.y, acc2[0][3]);
            PMA(a0.z, a0.w, b3.z, b3.w, acc2[0][3]);

            PMA(a1.x, a1.y, b0.x, b0.y, acc2[1][0]);
            PMA(a1.z, a1.w, b0.z, b0.w, acc2[1][0]);
            PMA(a1.x, a1.y, b1.x, b1.y, acc2[1][1]);
            PMA(a1.z, a1.w, b1.z, b1.w, acc2[1][1]);
            PMA(a1.x, a1.y, b2.x, b2.y, acc2[1][2]);
            PMA(a1.z, a1.w, b2.z, b2.w, acc2[1][2]);
            PMA(a1.x, a1.y, b3.x, b3.y, acc2[1][3]);
            PMA(a1.z, a1.w, b3.z, b3.w, acc2[1][3]);
        }
        __syncthreads();
    }

    xq[xr][t & 7] = xpart;
    __syncthreads();

    // Epilogue: unpack, divide, gate, store, per-row argmax key.
    #pragma unroll
    for (int i = 0; i < 2; i++) {
        int r = 2 * ty + i;
        int n = rowBase + r;
        float xs = ((xq[r][0] + xq[r][1]) + (xq[r][2] + xq[r][3]))
                 + ((xq[r][4] + xq[r][5]) + (xq[r][6] + xq[r][7]));
        unsigned long long bk = 0ull;
        #pragma unroll
        for (int j = 0; j < 4; j++) {
            int c = colBase + tx + 16 * j;
            float lo, hi;
            asm("mov.b64 {%0, %1}, %2;" : "=f"(lo), "=f"(hi) : "l"(acc2[i][j]));
            float m = (lo + hi) / xs;                  // exact division, as reference
            float g = (m >= VIG) ? m : 0.f;
            out[(size_t)n * C_CATS + c] = g;
            // order-preserving key: larger value wins; ties -> smaller column
            unsigned long long key =
                ((unsigned long long)__float_as_uint(g) << 32) |
                (unsigned long long)(unsigned)(C_CATS - 1 - c);
            if (key > bk) bk = key;
        }
        atomicMax(&skey[r], bk);
    }
    __syncthreads();

    // Cross-block argmax finalization (threadfence reduction over 8 col-blocks).
    if (t < BM) {
        int n = rowBase + t;
        atomicMax(&g_key[n], skey[t]);
        __threadfence();
        unsigned old = atomicAdd(&g_cnt[n], 1u);
        if (old == NCB - 1) {                              // last column-block for this row
            __threadfence();
            unsigned long long k = atomicMax(&g_key[n], 0ull);   // atomic read
            if (idx_out)
                idx_out[n] = (float)(C_CATS - 1 - (unsigned)(k & 0xffffffffull));
            g_key[n] = 0ull;                               // self-clean for next replay
            g_cnt[n] = 0u;
        }
    }
}

// ---------------------------------------------------------------------------
extern "C" void kernel_launch(void* const* d_in, const int* in_sizes, int n_in,
                              void* d_out, int out_size) {
    const float* x = (const float*)d_in[0];
    const float* w = (const float*)d_in[1];
    float* out = (float*)d_out;

    float* idx_out = (out_size >= N_ROWS * C_CATS + N_ROWS)
                   ? out + (size_t)N_ROWS * C_CATS : nullptr;

    dim3 grid(C_CATS / BN, N_ROWS / BM);   // (8, 16) = 128 blocks
    fused_kernel<<<grid, 512>>>(x, w, out, idx_out);
}

// round 8
// speedup vs baseline: 1.0151x; 1.0151x over previous
#include <cuda_runtime.h>

// FuzzyARTMAP single fused kernel: match scores + row sums + argmax.
// N=1024, D=256, C=512, fp32. match[n,c] = sum_d min(x,w) / sum_d x; gate 0.75;
// first-occurrence argmax.
//
// R8: best-of-all-rounds recombination. 256 threads, 4x4 micro-tile (the measured-
// fastest compute core, 33% fewer LDS per min-op than 2x4), float4 LDS, fused x
// row-sums, LDG register prefetch double-buffering, and in-kernel argmax
// finalization via threadfence reduction (saves the 4.3us decode launch).

#define N_ROWS 1024
#define D_DIM  256
#define C_CATS 512
#define VIG    0.75f

#define BM 64
#define BN 64
#define BK 64
#define NCB (C_CATS / BN)     // column-blocks per row = 8
#define LSTRIDE 68            // 16B-aligned rows

__device__ unsigned long long g_key[N_ROWS];   // zero at load; self-reset each launch
__device__ unsigned int       g_cnt[N_ROWS];   // zero at load; self-reset each launch

// ---------------------------------------------------------------------------
__global__ __launch_bounds__(256) void fused_kernel(const float* __restrict__ x,
                                                    const float* __restrict__ w,
                                                    float* __restrict__ out,
                                                    float* __restrict__ idx_out) {
    __shared__ float As[BM][LSTRIDE];             // x tile [m][k]
    __shared__ float Bs[BN][LSTRIDE];             // w tile [c][k]
    __shared__ float xq[BM][4];                   // per-row quarter sums of x
    __shared__ unsigned long long skey[BM];       // per-row best (val, col) key

    const int t  = threadIdx.x;
    const int tx = t & 15;        // 16 thread-columns
    const int ty = t >> 4;        // 16 thread-rows (4 rows each)
    const int rowBase = blockIdx.y * BM;
    const int colBase = blockIdx.x * BN;

    float acc[4][4];
    #pragma unroll
    for (int i = 0; i < 4; i++)
        #pragma unroll
        for (int j = 0; j < 4; j++) acc[i][j] = 0.f;

    float xpart = 0.f;             // x row-sum duty: 4 threads per row, 16 elems each
    const int xr = t >> 2;
    const int xc = (t & 3) * 16;

    if (t < BM) skey[t] = 0ull;

    // Tile-load mapping: 4 float4 per array per thread (rows lr+16i).
    const int lr = t >> 4;        // 0..15
    const int lc = t & 15;        // float4 column (BK/4 = 16)

    // Prefetch iteration 0 into registers.
    float4 pa[4], pb[4];
    #pragma unroll
    for (int i = 0; i < 4; i++) {
        int r = lr + 16 * i;
        pa[i] = *(const float4*)(x + (size_t)(rowBase + r) * D_DIM + 4 * lc);
        pb[i] = *(const float4*)(w + (size_t)(colBase + r) * D_DIM + 4 * lc);
    }

    #pragma unroll
    for (int it = 0; it < D_DIM / BK; it++) {
        #pragma unroll
        for (int i = 0; i < 4; i++) {
            int r = lr + 16 * i;
            *(float4*)&As[r][4 * lc] = pa[i];
            *(float4*)&Bs[r][4 * lc] = pb[i];
        }
        __syncthreads();

        // Prefetch next iteration's tiles (hidden behind the math below).
        if (it + 1 < D_DIM / BK) {
            int k0 = (it + 1) * BK;
            #pragma unroll
            for (int i = 0; i < 4; i++) {
                int r = lr + 16 * i;
                pa[i] = *(const float4*)(x + (size_t)(rowBase + r) * D_DIM + k0 + 4 * lc);
                pb[i] = *(const float4*)(w + (size_t)(colBase + r) * D_DIM + k0 + 4 * lc);
            }
        }

        // Fused row-sum: each thread sums a 16-wide quarter of one As row.
        {
            const float* rp = &As[xr][xc];
            float s = 0.f;
            #pragma unroll
            for (int u = 0; u < 4; u++) {
                float4 v = *(const float4*)(rp + 4 * u);
                s += (v.x + v.y) + (v.z + v.w);
            }
            xpart += s;
        }

        #pragma unroll 4
        for (int k = 0; k < BK; k += 4) {
            float4 a0 = *(const float4*)&As[4 * ty + 0][k];
            float4 a1 = *(const float4*)&As[4 * ty + 1][k];
            float4 a2 = *(const float4*)&As[4 * ty + 2][k];
            float4 a3 = *(const float4*)&As[4 * ty + 3][k];
            float4 b0 = *(const float4*)&Bs[tx +  0][k];
            float4 b1 = *(const float4*)&Bs[tx + 16][k];
            float4 b2 = *(const float4*)&Bs[tx + 32][k];
            float4 b3 = *(const float4*)&Bs[tx + 48][k];

            #define STEP(F)                                \
                acc[0][0] += fminf(a0.F, b0.F);           \
                acc[0][1] += fminf(a0.F, b1.F);           \
                acc[0][2] += fminf(a0.F, b2.F);           \
                acc[0][3] += fminf(a0.F, b3.F);           \
                acc[1][0] += fminf(a1.F, b0.F);           \
                acc[1][1] += fminf(a1.F, b1.F);           \
                acc[1][2] += fminf(a1.F, b2.F);           \
                acc[1][3] += fminf(a1.F, b3.F);           \
                acc[2][0] += fminf(a2.F, b0.F);           \
                acc[2][1] += fminf(a2.F, b1.F);           \
                acc[2][2] += fminf(a2.F, b2.F);           \
                acc[2][3] += fminf(a2.F, b3.F);           \
                acc[3][0] += fminf(a3.F, b0.F);           \
                acc[3][1] += fminf(a3.F, b1.F);           \
                acc[3][2] += fminf(a3.F, b2.F);           \
                acc[3][3] += fminf(a3.F, b3.F);
            STEP(x) STEP(y) STEP(z) STEP(w)
            #undef STEP
        }
        __syncthreads();
    }

    xq[xr][t & 3] = xpart;
    __syncthreads();

    // Epilogue: divide, gate, store, per-row argmax key.
    #pragma unroll
    for (int i = 0; i < 4; i++) {
        int r = 4 * ty + i;
        int n = rowBase + r;
        float xs = (xq[r][0] + xq[r][1]) + (xq[r][2] + xq[r][3]);
        unsigned long long bk = 0ull;
        #pragma unroll
        for (int j = 0; j < 4; j++) {
            int c = colBase + tx + 16 * j;
            float m = acc[i][j] / xs;                  // exact division, as reference
            float g = (m >= VIG) ? m : 0.f;
            out[(size_t)n * C_CATS + c] = g;
            // order-preserving key: larger value wins; ties -> smaller column
            unsigned long long key =
                ((unsigned long long)__float_as_uint(g) << 32) |
                (unsigned long long)(unsigned)(C_CATS - 1 - c);
            if (key > bk) bk = key;
        }
        atomicMax(&skey[r], bk);
    }
    __syncthreads();

    // Cross-block argmax finalization (threadfence reduction over 8 col-blocks).
    if (t < BM) {
        int n = rowBase + t;
        atomicMax(&g_key[n], skey[t]);
        __threadfence();
        unsigned old = atomicAdd(&g_cnt[n], 1u);
        if (old == NCB - 1) {                              // last column-block for this row
            __threadfence();
            unsigned long long k = atomicMax(&g_key[n], 0ull);   // atomic read
            if (idx_out)
                idx_out[n] = (float)(C_CATS - 1 - (unsigned)(k & 0xffffffffull));
            g_key[n] = 0ull;                               // self-clean for next replay
            g_cnt[n] = 0u;
        }
    }
}

// ---------------------------------------------------------------------------
extern "C" void kernel_launch(void* const* d_in, const int* in_sizes, int n_in,
                              void* d_out, int out_size) {
    const float* x = (const float*)d_in[0];
    const float* w = (const float*)d_in[1];
    float* out = (float*)d_out;

    float* idx_out = (out_size >= N_ROWS * C_CATS + N_ROWS)
                   ? out + (size_t)N_ROWS * C_CATS : nullptr;

    dim3 grid(C_CATS / BN, N_ROWS / BM);   // (8, 16) = 128 blocks
    fused_kernel<<<grid, 256>>>(x, w, out, idx_out);
}

// round 9
// speedup vs baseline: 1.0275x; 1.0122x over previous
#include <cuda_runtime.h>

// FuzzyARTMAP single fused kernel: match scores + row sums + argmax.
// N=1024, D=256, C=512, fp32. match[n,c] = sum_d min(x,w) / sum_d x; gate 0.75;
// first-occurrence argmax.
//
// R9: 512 threads = two 256-thread k-halves, each the proven 4x4 micro-tile over
// a 32-wide k slice (in-block split-K). Doubles warps/SMSP (2->4) while keeping
// the 16-accumulator ILP of the 4x4 core. No LDG prefetch (measured regression).
// Halves combine via smem; argmax finalized in-kernel (threadfence reduction).

#define N_ROWS 1024
#define D_DIM  256
#define C_CATS 512
#define VIG    0.75f

#define BM 64
#define BN 64
#define BK 64
#define NCB (C_CATS / BN)     // column-blocks per row = 8
#define LSTRIDE 68            // 16B-aligned rows; conflict-free per 8-lane LDS.128 phase

__device__ unsigned long long g_key[N_ROWS];   // zero at load; self-reset each launch
__device__ unsigned int       g_cnt[N_ROWS];   // zero at load; self-reset each launch

// ---------------------------------------------------------------------------
__global__ __launch_bounds__(512) void fused_kernel(const float* __restrict__ x,
                                                    const float* __restrict__ w,
                                                    float* __restrict__ out,
                                                    float* __restrict__ idx_out) {
    __shared__ float As[BM][LSTRIDE];             // x tile [m][k]
    __shared__ float Bs[BN][LSTRIDE];             // w tile [c][k]
    __shared__ float xq[BM][8];                   // per-row 1/8 sums of x
    __shared__ unsigned long long skey[BM];       // per-row best (val, col) key

    const int t   = threadIdx.x;
    const int kh  = t >> 8;        // k-half: 0 or 1
    const int tt  = t & 255;       // id within half
    const int tx  = tt & 15;       // 16 thread-columns
    const int ty  = tt >> 4;       // 16 thread-rows (4 rows each)
    const int rowBase = blockIdx.y * BM;
    const int colBase = blockIdx.x * BN;
    const int kbase   = kh * (BK / 2);

    float acc[4][4];
    #pragma unroll
    for (int i = 0; i < 4; i++)
        #pragma unroll
        for (int j = 0; j < 4; j++) acc[i][j] = 0.f;

    float xpart = 0.f;             // x row-sum duty: 8 threads per row, 8 elems each
    const int xr = t >> 3;
    const int xc = (t & 7) * 8;

    if (t < BM) skey[t] = 0ull;

    for (int k0 = 0; k0 < D_DIM; k0 += BK) {
        // Load 64x64 tiles: 1024 float4 per array, 2 per thread.
        #pragma unroll
        for (int i = 0; i < 2; i++) {
            int idx = t + 512 * i;
            int r   = idx >> 4;
            int c4  = idx & 15;
            *(float4*)&As[r][4 * c4] =
                *(const float4*)(x + (size_t)(rowBase + r) * D_DIM + k0 + 4 * c4);
            *(float4*)&Bs[r][4 * c4] =
                *(const float4*)(w + (size_t)(colBase + r) * D_DIM + k0 + 4 * c4);
        }
        __syncthreads();

        // Fused row-sum: each thread sums an 8-wide slice of one As row.
        {
            float4 v0 = *(const float4*)&As[xr][xc];
            float4 v1 = *(const float4*)&As[xr][xc + 4];
            xpart += (v0.x + v0.y) + (v0.z + v0.w) + (v1.x + v1.y) + (v1.z + v1.w);
        }

        // This half processes k in [kbase, kbase+32) with the 4x4 core.
        #pragma unroll
        for (int kk = 0; kk < BK / 2; kk += 4) {
            const int k = kbase + kk;
            float4 a0 = *(const float4*)&As[4 * ty + 0][k];
            float4 a1 = *(const float4*)&As[4 * ty + 1][k];
            float4 a2 = *(const float4*)&As[4 * ty + 2][k];
            float4 a3 = *(const float4*)&As[4 * ty + 3][k];
            float4 b0 = *(const float4*)&Bs[tx +  0][k];
            float4 b1 = *(const float4*)&Bs[tx + 16][k];
            float4 b2 = *(const float4*)&Bs[tx + 32][k];
            float4 b3 = *(const float4*)&Bs[tx + 48][k];

            #define STEP(F)                                \
                acc[0][0] += fminf(a0.F, b0.F);           \
                acc[0][1] += fminf(a0.F, b1.F);           \
                acc[0][2] += fminf(a0.F, b2.F);           \
                acc[0][3] += fminf(a0.F, b3.F);           \
                acc[1][0] += fminf(a1.F, b0.F);           \
                acc[1][1] += fminf(a1.F, b1.F);           \
                acc[1][2] += fminf(a1.F, b2.F);           \
                acc[1][3] += fminf(a1.F, b3.F);           \
                acc[2][0] += fminf(a2.F, b0.F);           \
                acc[2][1] += fminf(a2.F, b1.F);           \
                acc[2][2] += fminf(a2.F, b2.F);           \
                acc[2][3] += fminf(a2.F, b3.F);           \
                acc[3][0] += fminf(a3.F, b0.F);           \
                acc[3][1] += fminf(a3.F, b1.F);           \
                acc[3][2] += fminf(a3.F, b2.F);           \
                acc[3][3] += fminf(a3.F, b3.F);
            STEP(x) STEP(y) STEP(z) STEP(w)
            #undef STEP
        }
        __syncthreads();
    }

    // Publish x row-sum slices.
    xq[t >> 3][t & 7] = xpart;

    // Combine k-halves: kh=1 stages its 16 partials in the (now dead) As region.
    float* stage = &As[0][0];                     // 256 threads x 16 floats = 16KB <= As
    if (kh) {
        #pragma unroll
        for (int i = 0; i < 4; i++)
            *(float4*)&stage[tt * 16 + 4 * i] =
                make_float4(acc[i][0], acc[i][1], acc[i][2], acc[i][3]);
    }
    __syncthreads();

    if (!kh) {
        #pragma unroll
        for (int i = 0; i < 4; i++) {
            float4 p = *(const float4*)&stage[tt * 16 + 4 * i];
            acc[i][0] += p.x; acc[i][1] += p.y; acc[i][2] += p.z; acc[i][3] += p.w;
        }

        // Epilogue: divide, gate, store, per-row argmax key.
        #pragma unroll
        for (int i = 0; i < 4; i++) {
            int r = 4 * ty + i;
            int n = rowBase + r;
            float xs = ((xq[r][0] + xq[r][1]) + (xq[r][2] + xq[r][3]))
                     + ((xq[r][4] + xq[r][5]) + (xq[r][6] + xq[r][7]));
            unsigned long long bk = 0ull;
            #pragma unroll
            for (int j = 0; j < 4; j++) {
                int c = colBase + tx + 16 * j;
                float m = acc[i][j] / xs;                  // exact division, as reference
                float g = (m >= VIG) ? m : 0.f;
                out[(size_t)n * C_CATS + c] = g;
                // order-preserving key: larger value wins; ties -> smaller column
                unsigned long long key =
                    ((unsigned long long)__float_as_uint(g) << 32) |
                    (unsigned long long)(unsigned)(C_CATS - 1 - c);
                if (key > bk) bk = key;
            }
            atomicMax(&skey[r], bk);
        }
    }
    __syncthreads();

    // Cross-block argmax finalization (threadfence reduction over 8 col-blocks).
    if (t < BM) {
        int n = rowBase + t;
        atomicMax(&g_key[n], skey[t]);
        __threadfence();
        unsigned old = atomicAdd(&g_cnt[n], 1u);
        if (old == NCB - 1) {                              // last column-block for this row
            __threadfence();
            unsigned long long k = atomicMax(&g_key[n], 0ull);   // atomic read
            if (idx_out)
                idx_out[n] = (float)(C_CATS - 1 - (unsigned)(k & 0xffffffffull));
            g_key[n] = 0ull;                               // self-clean for next replay
            g_cnt[n] = 0u;
        }
    }
}

// ---------------------------------------------------------------------------
extern "C" void kernel_launch(void* const* d_in, const int* in_sizes, int n_in,
                              void* d_out, int out_size) {
    const float* x = (const float*)d_in[0];
    const float* w = (const float*)d_in[1];
    float* out = (float*)d_out;

    float* idx_out = (out_size >= N_ROWS * C_CATS + N_ROWS)
                   ? out + (size_t)N_ROWS * C_CATS : nullptr;

    dim3 grid(C_CATS / BN, N_ROWS / BM);   // (8, 16) = 128 blocks
    fused_kernel<<<grid, 512>>>(x, w, out, idx_out);
}